// round 9
// baseline (speedup 1.0000x reference)
#include <cuda_runtime.h>
#include <cuda_fp16.h>
#include <math.h>
#include <stdint.h>

#define N_NODES 100000
#define N_EDGES 1600000
#define NFEAT   512
#define HIDDEN  128
#define NCLASS  40

// ---------------- scratch (device globals; no allocation allowed) ----------
__device__ __half g_support1h[(long)N_NODES * HIDDEN]; // X @ W1 (fp16)
__device__ __half g_support2h[(long)N_NODES * NCLASS]; // A(relu(...)) @ W2 (fp16)
__device__ __half g_W1t[(long)NFEAT * HIDDEN];         // W1^T fp16 [n][k]
__device__ int    g_deg[N_NODES];
__device__ int    g_row_ptr[N_NODES + 1];
__device__ int    g_cursor[N_NODES];
__device__ int2   g_edges[N_EDGES];                    // {src, val bits}
__device__ int    g_psum[128];

#define SCAN_TILE 1024
#define N_SBLOCKS ((N_NODES + SCAN_TILE - 1) / SCAN_TILE)   // 98

// ---------------- CSR build --------------------------------------------------
__global__ void zero_deg_kernel() {
    int i = blockIdx.x * blockDim.x + threadIdx.x;
    if (i < N_NODES) g_deg[i] = 0;
}

__global__ void hist_kernel(const int* __restrict__ dst) {
    int i = blockIdx.x * blockDim.x + threadIdx.x;
    if (i < N_EDGES) atomicAdd(&g_deg[dst[i]], 1);
}

__global__ __launch_bounds__(256) void scan_phase1() {
    int b = blockIdx.x, tid = threadIdx.x;
    int lane = tid & 31, warp = tid >> 5;
    int base = b * SCAN_TILE + tid * 4;
    int s = 0;
#pragma unroll
    for (int j = 0; j < 4; j++) {
        int i = base + j;
        if (i < N_NODES) s += g_deg[i];
    }
#pragma unroll
    for (int off = 16; off > 0; off >>= 1)
        s += __shfl_xor_sync(0xFFFFFFFFu, s, off);
    __shared__ int wsum[8];
    if (lane == 0) wsum[warp] = s;
    __syncthreads();
    if (tid == 0) {
        int t = 0;
#pragma unroll
        for (int w = 0; w < 8; w++) t += wsum[w];
        g_psum[b] = t;
    }
}

__global__ __launch_bounds__(128) void scan_phase2() {
    int tid = threadIdx.x;
    __shared__ int sh[128];
    int v = (tid < N_SBLOCKS) ? g_psum[tid] : 0;
    sh[tid] = v;
    __syncthreads();
#pragma unroll
    for (int off = 1; off < 128; off <<= 1) {
        int t = (tid >= off) ? sh[tid - off] : 0;
        __syncthreads();
        sh[tid] += t;
        __syncthreads();
    }
    if (tid < N_SBLOCKS) g_psum[tid] = sh[tid] - v;
}

__global__ __launch_bounds__(256) void scan_phase3() {
    int b = blockIdx.x, tid = threadIdx.x;
    int lane = tid & 31, warp = tid >> 5;
    int base = b * SCAN_TILE + tid * 4;
    int v[4], tsum = 0;
#pragma unroll
    for (int j = 0; j < 4; j++) {
        int i = base + j;
        v[j] = (i < N_NODES) ? g_deg[i] : 0;
        tsum += v[j];
    }
    int incl = tsum;
#pragma unroll
    for (int off = 1; off < 32; off <<= 1) {
        int n = __shfl_up_sync(0xFFFFFFFFu, incl, off);
        if (lane >= off) incl += n;
    }
    __shared__ int wtot[8];
    if (lane == 31) wtot[warp] = incl;
    __syncthreads();
    if (warp == 0 && lane < 8) {
        int wv = wtot[lane];
        int wincl = wv;
#pragma unroll
        for (int off = 1; off < 8; off <<= 1) {
            int n = __shfl_up_sync(0xFFu, wincl, off);
            if (lane >= off) wincl += n;
        }
        wtot[lane] = wincl - wv;
    }
    __syncthreads();
    int run = g_psum[b] + wtot[warp] + incl - tsum;
#pragma unroll
    for (int j = 0; j < 4; j++) {
        int i = base + j;
        if (i < N_NODES) { g_row_ptr[i] = run; g_cursor[i] = run; }
        run += v[j];
    }
    if (b == 0 && tid == 0) g_row_ptr[N_NODES] = N_EDGES;
}

__global__ void scatter_kernel(const int* __restrict__ src,
                               const int* __restrict__ dst,
                               const float* __restrict__ val) {
    int i = blockIdx.x * blockDim.x + threadIdx.x;
    if (i < N_EDGES) {
        int d = dst[i];
        int p = atomicAdd(&g_cursor[d], 1);
        g_edges[p] = make_int2(src[i], __float_as_int(val[i]));
    }
}

// ---------------- W1 transpose + fp16 convert --------------------------------
__global__ __launch_bounds__(256) void w1t_kernel(const float* __restrict__ W1) {
    int i = blockIdx.x * blockDim.x + threadIdx.x;
    if (i < NFEAT * HIDDEN) {
        int k = i / HIDDEN, n = i % HIDDEN;
        g_W1t[(long)n * NFEAT + k] = __float2half_rn(W1[i]);
    }
}

// ---------------- GEMM1 (fp16 tensor cores, reg-staged A + cp.async B) ------
#define G1_BM 128
#define G1_BK 32
#define HSTR 40

__device__ __forceinline__ void cp16b(uint32_t dst, const void* src) {
    asm volatile("cp.async.cg.shared.global [%0], [%1], 16;\n"
                 :: "r"(dst), "l"(src));
}

__global__ __launch_bounds__(256, 2) void gemm1_f16_kernel(const float* __restrict__ A) {
    __shared__ __half Ah[2][G1_BM * HSTR];
    __shared__ __half Bh[2][HIDDEN * HSTR];

    const int tid  = threadIdx.x;
    const int warp = tid >> 5;
    const int lane = tid & 31;
    const int g = lane >> 2;
    const int t = lane & 3;
    const int wm = (warp >> 2) * 64;
    const int wn = (warp & 3) * 32;
    const int block_row = blockIdx.x * G1_BM;

    float4 areg[4];
    float acc[4][4][4];
#pragma unroll
    for (int mi = 0; mi < 4; mi++)
#pragma unroll
        for (int ni = 0; ni < 4; ni++)
#pragma unroll
            for (int q = 0; q < 4; q++) acc[mi][ni][q] = 0.f;

    auto ldgA = [&](int k0) {
#pragma unroll
        for (int j = 0; j < 4; j++) {
            int chunk = tid + j * 256;
            int row = chunk >> 3;
            int col = (chunk & 7) * 4;
            int gr = block_row + row;
            if (gr < N_NODES)
                areg[j] = *(const float4*)&A[(long)gr * NFEAT + k0 + col];
            else
                areg[j] = make_float4(0.f, 0.f, 0.f, 0.f);
        }
    };
    auto stsA = [&](int buf) {
#pragma unroll
        for (int j = 0; j < 4; j++) {
            int chunk = tid + j * 256;
            int row = chunk >> 3;
            int col = (chunk & 7) * 4;
            uint2 h;
            *(__half2*)&h.x = __floats2half2_rn(areg[j].x, areg[j].y);
            *(__half2*)&h.y = __floats2half2_rn(areg[j].z, areg[j].w);
            *(uint2*)&Ah[buf][row * HSTR + col] = h;
        }
    };
    auto cpB = [&](int buf, int k0) {
        uint32_t base = (uint32_t)__cvta_generic_to_shared(&Bh[buf][0]);
#pragma unroll
        for (int j = 0; j < 2; j++) {
            int chunk = tid + j * 256;
            int n = chunk >> 2;
            int kc = (chunk & 3) * 8;
            cp16b(base + (n * HSTR + kc) * 2, &g_W1t[(long)n * NFEAT + k0 + kc]);
        }
    };

    const int NT = NFEAT / G1_BK;
    ldgA(0);
    cpB(0, 0);
    asm volatile("cp.async.commit_group;\n");

    for (int kt = 0; kt < NT; kt++) {
        int buf = kt & 1;
        stsA(buf);
        if (kt + 1 < NT) {
            ldgA((kt + 1) * G1_BK);
            cpB(buf ^ 1, (kt + 1) * G1_BK);
            asm volatile("cp.async.commit_group;\n");
            asm volatile("cp.async.wait_group 1;\n");
        } else {
            asm volatile("cp.async.wait_group 0;\n");
        }
        __syncthreads();

#pragma unroll
        for (int ks = 0; ks < 2; ks++) {
            const int kb = ks * 16;
            uint32_t af[4][4], bf[4][2];
#pragma unroll
            for (int mi = 0; mi < 4; mi++) {
                int r0 = wm + mi * 16 + g;
                af[mi][0] = *(uint32_t*)&Ah[buf][(r0)     * HSTR + kb + 2 * t];
                af[mi][1] = *(uint32_t*)&Ah[buf][(r0 + 8) * HSTR + kb + 2 * t];
                af[mi][2] = *(uint32_t*)&Ah[buf][(r0)     * HSTR + kb + 8 + 2 * t];
                af[mi][3] = *(uint32_t*)&Ah[buf][(r0 + 8) * HSTR + kb + 8 + 2 * t];
            }
#pragma unroll
            for (int ni = 0; ni < 4; ni++) {
                int c = wn + ni * 8 + g;
                bf[ni][0] = *(uint32_t*)&Bh[buf][c * HSTR + kb + 2 * t];
                bf[ni][1] = *(uint32_t*)&Bh[buf][c * HSTR + kb + 8 + 2 * t];
            }
#pragma unroll
            for (int mi = 0; mi < 4; mi++) {
#pragma unroll
                for (int ni = 0; ni < 4; ni++) {
                    asm volatile(
                        "mma.sync.aligned.m16n8k16.row.col.f32.f16.f16.f32 "
                        "{%0,%1,%2,%3}, {%4,%5,%6,%7}, {%8,%9}, {%0,%1,%2,%3};"
                        : "+f"(acc[mi][ni][0]), "+f"(acc[mi][ni][1]),
                          "+f"(acc[mi][ni][2]), "+f"(acc[mi][ni][3])
                        : "r"(af[mi][0]), "r"(af[mi][1]), "r"(af[mi][2]), "r"(af[mi][3]),
                          "r"(bf[ni][0]), "r"(bf[ni][1]));
                }
            }
        }
        __syncthreads();
    }

#pragma unroll
    for (int mi = 0; mi < 4; mi++) {
        int r0 = block_row + wm + mi * 16 + g;
        int r1 = r0 + 8;
#pragma unroll
        for (int ni = 0; ni < 4; ni++) {
            int c = wn + ni * 8 + 2 * t;
            if (r0 < N_NODES)
                *(__half2*)&g_support1h[(long)r0 * HIDDEN + c] =
                    __floats2half2_rn(acc[mi][ni][0], acc[mi][ni][1]);
            if (r1 < N_NODES)
                *(__half2*)&g_support1h[(long)r1 * HIDDEN + c] =
                    __floats2half2_rn(acc[mi][ni][2], acc[mi][ni][3]);
        }
    }
}

// ---------------- Fused SpMM1 + GEMM2 ----------------------------------------
// Block handles 128 nodes. Phase 1: each of 8 warps aggregates 16 nodes
// (relu(agg + b1) -> fp16 smem tile). Phase 2: fp16 MMA tile @ W2 -> support2h.
#define H_STRIDE 136
#define FUSE_SMEM ((128 * H_STRIDE + 40 * H_STRIDE) * 2)

__global__ __launch_bounds__(256) void spmm1_gemm2_kernel(const float* __restrict__ b1,
                                                          const float* __restrict__ W2) {
    extern __shared__ __half sh2[];
    __half* shH = sh2;                    // [128][H_STRIDE]
    __half* shW = sh2 + 128 * H_STRIDE;   // [40][H_STRIDE]  (shW[n][k])
    const int tid  = threadIdx.x;
    const int warp = tid >> 5;
    const int lane = tid & 31;
    const int g = lane >> 2;
    const int t = lane & 3;
    const int row0 = blockIdx.x * 128;

    // W2 fp32 -> fp16 transposed
    for (int e = tid; e < HIDDEN * NCLASS; e += 256) {
        int k = e / NCLASS, n = e % NCLASS;
        shW[n * H_STRIDE + k] = __float2half_rn(W2[e]);
    }

    // phase 1: aggregate 16 nodes per warp
    float4 bb = *(const float4*)&b1[lane * 4];
#pragma unroll 1
    for (int i = 0; i < 16; i++) {
        int r = warp * 16 + i;
        int node = row0 + r;
        uint2 o;
        if (node < N_NODES) {
            int beg = g_row_ptr[node];
            int end = g_row_ptr[node + 1];
            float4 acc = make_float4(0.f, 0.f, 0.f, 0.f);
            for (int e = beg; e < end; e++) {
                int2  ed = __ldcs(&g_edges[e]);
                float v  = __int_as_float(ed.y);
                uint2 u = *(const uint2*)&g_support1h[(long)ed.x * HIDDEN + lane * 4];
                float2 f0 = __half22float2(*(__half2*)&u.x);
                float2 f1 = __half22float2(*(__half2*)&u.y);
                acc.x += v * f0.x; acc.y += v * f0.y;
                acc.z += v * f1.x; acc.w += v * f1.y;
            }
            acc.x = fmaxf(acc.x + bb.x, 0.f);
            acc.y = fmaxf(acc.y + bb.y, 0.f);
            acc.z = fmaxf(acc.z + bb.z, 0.f);
            acc.w = fmaxf(acc.w + bb.w, 0.f);
            *(__half2*)&o.x = __floats2half2_rn(acc.x, acc.y);
            *(__half2*)&o.y = __floats2half2_rn(acc.z, acc.w);
        } else {
            o = make_uint2(0, 0);
        }
        *(uint2*)&shH[r * H_STRIDE + lane * 4] = o;
    }
    __syncthreads();

    // phase 2: MMA 128x40x128 (same as gemm2_h)
    const int wm = warp * 16;
    float acc[5][4];
#pragma unroll
    for (int n = 0; n < 5; n++)
#pragma unroll
        for (int q = 0; q < 4; q++) acc[n][q] = 0.f;

#pragma unroll
    for (int ks = 0; ks < 8; ks++) {
        const int k0 = ks * 16;
        uint32_t a0 = *(uint32_t*)&shH[(wm + g)     * H_STRIDE + k0 + 2 * t];
        uint32_t a1 = *(uint32_t*)&shH[(wm + g + 8) * H_STRIDE + k0 + 2 * t];
        uint32_t a2 = *(uint32_t*)&shH[(wm + g)     * H_STRIDE + k0 + 8 + 2 * t];
        uint32_t a3 = *(uint32_t*)&shH[(wm + g + 8) * H_STRIDE + k0 + 8 + 2 * t];
#pragma unroll
        for (int n = 0; n < 5; n++) {
            uint32_t b0 = *(uint32_t*)&shW[(n * 8 + g) * H_STRIDE + k0 + 2 * t];
            uint32_t b1w = *(uint32_t*)&shW[(n * 8 + g) * H_STRIDE + k0 + 8 + 2 * t];
            asm volatile(
                "mma.sync.aligned.m16n8k16.row.col.f32.f16.f16.f32 "
                "{%0,%1,%2,%3}, {%4,%5,%6,%7}, {%8,%9}, {%0,%1,%2,%3};"
                : "+f"(acc[n][0]), "+f"(acc[n][1]), "+f"(acc[n][2]), "+f"(acc[n][3])
                : "r"(a0), "r"(a1), "r"(a2), "r"(a3), "r"(b0), "r"(b1w));
        }
    }

#pragma unroll
    for (int n = 0; n < 5; n++) {
        int c = n * 8 + 2 * t;
        int r0 = row0 + wm + g;
        int r1 = r0 + 8;
        if (r0 < N_NODES)
            *(__half2*)&g_support2h[(long)r0 * NCLASS + c] =
                __floats2half2_rn(acc[n][0], acc[n][1]);
        if (r1 < N_NODES)
            *(__half2*)&g_support2h[(long)r1 * NCLASS + c] =
                __floats2half2_rn(acc[n][2], acc[n][3]);
    }
}

// ---------------- SpMM2 + bias + log_softmax --------------------------------
__global__ __launch_bounds__(256) void spmm2_softmax_kernel(const float* __restrict__ b2,
                                                            float* __restrict__ out) {
    int warp = (blockIdx.x * blockDim.x + threadIdx.x) >> 5;
    int lane = threadIdx.x & 31;
    if (warp >= N_NODES) return;
    int beg = g_row_ptr[warp];
    int end = g_row_ptr[warp + 1];
    bool act = lane < 20;
    float a0 = 0.f, a1 = 0.f;
    for (int e = beg; e < end; e++) {
        int2  ed = __ldcs(&g_edges[e]);
        float v  = __int_as_float(ed.y);
        if (act) {
            uint32_t u = *(const uint32_t*)&g_support2h[(long)ed.x * NCLASS + 2 * lane];
            float2 f = __half22float2(*(__half2*)&u);
            a0 += v * f.x;
            a1 += v * f.y;
        }
    }
    float z0 = -INFINITY, z1 = -INFINITY;
    if (act) {
        z0 = a0 + b2[2 * lane];
        z1 = a1 + b2[2 * lane + 1];
    }
    float m = fmaxf(z0, z1);
#pragma unroll
    for (int off = 16; off > 0; off >>= 1)
        m = fmaxf(m, __shfl_xor_sync(0xFFFFFFFFu, m, off));
    float s = act ? (expf(z0 - m) + expf(z1 - m)) : 0.f;
#pragma unroll
    for (int off = 16; off > 0; off >>= 1)
        s += __shfl_xor_sync(0xFFFFFFFFu, s, off);
    float L = m + logf(s);
    if (act)
        *(float2*)&out[(long)warp * NCLASS + 2 * lane] = make_float2(z0 - L, z1 - L);
}

// ---------------- launch -----------------------------------------------------
extern "C" void kernel_launch(void* const* d_in, const int* in_sizes, int n_in,
                              void* d_out, int out_size) {
    const float* x        = (const float*)d_in[0];
    const int*   edge_src = (const int*)d_in[1];
    const int*   edge_dst = (const int*)d_in[2];
    const float* edge_val = (const float*)d_in[3];
    const float* W1       = (const float*)d_in[4];
    const float* b1       = (const float*)d_in[5];
    const float* W2       = (const float*)d_in[6];
    const float* b2       = (const float*)d_in[7];
    float* out = (float*)d_out;

    (void)in_sizes; (void)n_in; (void)out_size;

    static cudaStream_t s_csr = nullptr;
    static cudaEvent_t  ev_fork = nullptr, ev_join = nullptr;
    static bool s_init = false;
    if (!s_init) {
        cudaStreamCreateWithFlags(&s_csr, cudaStreamNonBlocking);
        cudaEventCreateWithFlags(&ev_fork, cudaEventDisableTiming);
        cudaEventCreateWithFlags(&ev_join, cudaEventDisableTiming);
        cudaFuncSetAttribute(spmm1_gemm2_kernel, cudaFuncAttributeMaxDynamicSharedMemorySize, FUSE_SMEM);
        s_init = true;
    }

    cudaEventRecord(ev_fork, 0);
    cudaStreamWaitEvent(s_csr, ev_fork, 0);

    zero_deg_kernel<<<(N_NODES + 255) / 256, 256, 0, s_csr>>>();
    hist_kernel<<<(N_EDGES + 255) / 256, 256, 0, s_csr>>>(edge_dst);
    scan_phase1<<<N_SBLOCKS, 256, 0, s_csr>>>();
    scan_phase2<<<1, 128, 0, s_csr>>>();
    scan_phase3<<<N_SBLOCKS, 256, 0, s_csr>>>();
    scatter_kernel<<<(N_EDGES + 255) / 256, 256, 0, s_csr>>>(edge_src, edge_dst, edge_val);
    cudaEventRecord(ev_join, s_csr);

    w1t_kernel<<<(NFEAT * HIDDEN + 255) / 256, 256>>>(W1);
    gemm1_f16_kernel<<<(N_NODES + G1_BM - 1) / G1_BM, 256>>>(x);

    cudaStreamWaitEvent(0, ev_join, 0);

    spmm1_gemm2_kernel<<<(N_NODES + 127) / 128, 256, FUSE_SMEM>>>(b1, W2);
    spmm2_softmax_kernel<<<(N_NODES * 32 + 255) / 256, 256>>>(b2, out);
}

// round 10
// speedup vs baseline: 1.1211x; 1.1211x over previous
#include <cuda_runtime.h>
#include <cuda_fp16.h>
#include <math.h>
#include <stdint.h>

#define N_NODES 100000
#define N_EDGES 1600000
#define NFEAT   512
#define HIDDEN  128
#define NCLASS  40

// ---------------- scratch (device globals; no allocation allowed) ----------
__device__ __half g_support1h[(long)N_NODES * HIDDEN]; // X @ W1 (fp16)
__device__ __half g_h1h[(long)N_NODES * HIDDEN];       // relu(agg + b1) (fp16)
__device__ __half g_support2h[(long)N_NODES * NCLASS]; // h1 @ W2 (fp16)
__device__ __half g_W1t[(long)NFEAT * HIDDEN];         // W1^T fp16 [n][k]
__device__ int    g_deg[N_NODES];
__device__ int    g_row_ptr[N_NODES + 1];
__device__ int    g_cursor[N_NODES];
__device__ int2   g_edges[N_EDGES];                    // {src, val bits}
__device__ int    g_psum[128];

#define SCAN_TILE 1024
#define N_SBLOCKS ((N_NODES + SCAN_TILE - 1) / SCAN_TILE)   // 98

// ---------------- CSR build --------------------------------------------------
__global__ void hist_kernel(const int* __restrict__ dst) {
    int i = blockIdx.x * blockDim.x + threadIdx.x;
    if (i < N_EDGES) atomicAdd(&g_deg[dst[i]], 1);
}

__global__ __launch_bounds__(256) void scan_phase1() {
    int b = blockIdx.x, tid = threadIdx.x;
    int lane = tid & 31, warp = tid >> 5;
    int base = b * SCAN_TILE + tid * 4;
    int s = 0;
#pragma unroll
    for (int j = 0; j < 4; j++) {
        int i = base + j;
        if (i < N_NODES) s += g_deg[i];
    }
#pragma unroll
    for (int off = 16; off > 0; off >>= 1)
        s += __shfl_xor_sync(0xFFFFFFFFu, s, off);
    __shared__ int wsum[8];
    if (lane == 0) wsum[warp] = s;
    __syncthreads();
    if (tid == 0) {
        int t = 0;
#pragma unroll
        for (int w = 0; w < 8; w++) t += wsum[w];
        g_psum[b] = t;
    }
}

__global__ __launch_bounds__(128) void scan_phase2() {
    int tid = threadIdx.x;
    __shared__ int sh[128];
    int v = (tid < N_SBLOCKS) ? g_psum[tid] : 0;
    sh[tid] = v;
    __syncthreads();
#pragma unroll
    for (int off = 1; off < 128; off <<= 1) {
        int t = (tid >= off) ? sh[tid - off] : 0;
        __syncthreads();
        sh[tid] += t;
        __syncthreads();
    }
    if (tid < N_SBLOCKS) g_psum[tid] = sh[tid] - v;
}

__global__ __launch_bounds__(256) void scan_phase3() {
    int b = blockIdx.x, tid = threadIdx.x;
    int lane = tid & 31, warp = tid >> 5;
    int base = b * SCAN_TILE + tid * 4;
    int v[4], tsum = 0;
#pragma unroll
    for (int j = 0; j < 4; j++) {
        int i = base + j;
        v[j] = (i < N_NODES) ? g_deg[i] : 0;
        tsum += v[j];
    }
    int incl = tsum;
#pragma unroll
    for (int off = 1; off < 32; off <<= 1) {
        int n = __shfl_up_sync(0xFFFFFFFFu, incl, off);
        if (lane >= off) incl += n;
    }
    __shared__ int wtot[8];
    if (lane == 31) wtot[warp] = incl;
    __syncthreads();
    if (warp == 0 && lane < 8) {
        int wv = wtot[lane];
        int wincl = wv;
#pragma unroll
        for (int off = 1; off < 8; off <<= 1) {
            int n = __shfl_up_sync(0xFFu, wincl, off);
            if (lane >= off) wincl += n;
        }
        wtot[lane] = wincl - wv;
    }
    __syncthreads();
    int run = g_psum[b] + wtot[warp] + incl - tsum;
#pragma unroll
    for (int j = 0; j < 4; j++) {
        int i = base + j;
        if (i < N_NODES) { g_row_ptr[i] = run; g_cursor[i] = run; }
        run += v[j];
    }
    if (b == 0 && tid == 0) g_row_ptr[N_NODES] = N_EDGES;
}

__global__ void scatter_kernel(const int* __restrict__ src,
                               const int* __restrict__ dst,
                               const float* __restrict__ val) {
    int i = blockIdx.x * blockDim.x + threadIdx.x;
    if (i < N_EDGES) {
        int d = dst[i];
        int p = atomicAdd(&g_cursor[d], 1);
        g_edges[p] = make_int2(src[i], __float_as_int(val[i]));
    }
}

// ---------------- W1 transpose + fp16 convert --------------------------------
__global__ __launch_bounds__(256) void w1t_kernel(const float* __restrict__ W1) {
    int i = blockIdx.x * blockDim.x + threadIdx.x;
    if (i < NFEAT * HIDDEN) {
        int k = i / HIDDEN, n = i % HIDDEN;
        g_W1t[(long)n * NFEAT + k] = __float2half_rn(W1[i]);
    }
}

// ---------------- GEMM1 (fp16 tensor cores, reg-staged A + cp.async B) ------
#define G1_BM 128
#define G1_BK 32
#define HSTR 40

__device__ __forceinline__ void cp16b(uint32_t dst, const void* src) {
    asm volatile("cp.async.cg.shared.global [%0], [%1], 16;\n"
                 :: "r"(dst), "l"(src));
}

__global__ __launch_bounds__(256, 2) void gemm1_f16_kernel(const float* __restrict__ A) {
    __shared__ __half Ah[2][G1_BM * HSTR];
    __shared__ __half Bh[2][HIDDEN * HSTR];

    const int tid  = threadIdx.x;
    const int warp = tid >> 5;
    const int lane = tid & 31;
    const int g = lane >> 2;
    const int t = lane & 3;
    const int wm = (warp >> 2) * 64;
    const int wn = (warp & 3) * 32;
    const int block_row = blockIdx.x * G1_BM;

    float4 areg[4];
    float acc[4][4][4];
#pragma unroll
    for (int mi = 0; mi < 4; mi++)
#pragma unroll
        for (int ni = 0; ni < 4; ni++)
#pragma unroll
            for (int q = 0; q < 4; q++) acc[mi][ni][q] = 0.f;

    auto ldgA = [&](int k0) {
#pragma unroll
        for (int j = 0; j < 4; j++) {
            int chunk = tid + j * 256;
            int row = chunk >> 3;
            int col = (chunk & 7) * 4;
            int gr = block_row + row;
            if (gr < N_NODES)
                areg[j] = *(const float4*)&A[(long)gr * NFEAT + k0 + col];
            else
                areg[j] = make_float4(0.f, 0.f, 0.f, 0.f);
        }
    };
    auto stsA = [&](int buf) {
#pragma unroll
        for (int j = 0; j < 4; j++) {
            int chunk = tid + j * 256;
            int row = chunk >> 3;
            int col = (chunk & 7) * 4;
            uint2 h;
            *(__half2*)&h.x = __floats2half2_rn(areg[j].x, areg[j].y);
            *(__half2*)&h.y = __floats2half2_rn(areg[j].z, areg[j].w);
            *(uint2*)&Ah[buf][row * HSTR + col] = h;
        }
    };
    auto cpB = [&](int buf, int k0) {
        uint32_t base = (uint32_t)__cvta_generic_to_shared(&Bh[buf][0]);
#pragma unroll
        for (int j = 0; j < 2; j++) {
            int chunk = tid + j * 256;
            int n = chunk >> 2;
            int kc = (chunk & 3) * 8;
            cp16b(base + (n * HSTR + kc) * 2, &g_W1t[(long)n * NFEAT + k0 + kc]);
        }
    };

    const int NT = NFEAT / G1_BK;
    ldgA(0);
    cpB(0, 0);
    asm volatile("cp.async.commit_group;\n");

    for (int kt = 0; kt < NT; kt++) {
        int buf = kt & 1;
        stsA(buf);
        if (kt + 1 < NT) {
            ldgA((kt + 1) * G1_BK);
            cpB(buf ^ 1, (kt + 1) * G1_BK);
            asm volatile("cp.async.commit_group;\n");
            asm volatile("cp.async.wait_group 1;\n");
        } else {
            asm volatile("cp.async.wait_group 0;\n");
        }
        __syncthreads();

#pragma unroll
        for (int ks = 0; ks < 2; ks++) {
            const int kb = ks * 16;
            uint32_t af[4][4], bf[4][2];
#pragma unroll
            for (int mi = 0; mi < 4; mi++) {
                int r0 = wm + mi * 16 + g;
                af[mi][0] = *(uint32_t*)&Ah[buf][(r0)     * HSTR + kb + 2 * t];
                af[mi][1] = *(uint32_t*)&Ah[buf][(r0 + 8) * HSTR + kb + 2 * t];
                af[mi][2] = *(uint32_t*)&Ah[buf][(r0)     * HSTR + kb + 8 + 2 * t];
                af[mi][3] = *(uint32_t*)&Ah[buf][(r0 + 8) * HSTR + kb + 8 + 2 * t];
            }
#pragma unroll
            for (int ni = 0; ni < 4; ni++) {
                int c = wn + ni * 8 + g;
                bf[ni][0] = *(uint32_t*)&Bh[buf][c * HSTR + kb + 2 * t];
                bf[ni][1] = *(uint32_t*)&Bh[buf][c * HSTR + kb + 8 + 2 * t];
            }
#pragma unroll
            for (int mi = 0; mi < 4; mi++) {
#pragma unroll
                for (int ni = 0; ni < 4; ni++) {
                    asm volatile(
                        "mma.sync.aligned.m16n8k16.row.col.f32.f16.f16.f32 "
                        "{%0,%1,%2,%3}, {%4,%5,%6,%7}, {%8,%9}, {%0,%1,%2,%3};"
                        : "+f"(acc[mi][ni][0]), "+f"(acc[mi][ni][1]),
                          "+f"(acc[mi][ni][2]), "+f"(acc[mi][ni][3])
                        : "r"(af[mi][0]), "r"(af[mi][1]), "r"(af[mi][2]), "r"(af[mi][3]),
                          "r"(bf[ni][0]), "r"(bf[ni][1]));
                }
            }
        }
        __syncthreads();
    }

#pragma unroll
    for (int mi = 0; mi < 4; mi++) {
        int r0 = block_row + wm + mi * 16 + g;
        int r1 = r0 + 8;
#pragma unroll
        for (int ni = 0; ni < 4; ni++) {
            int c = wn + ni * 8 + 2 * t;
            if (r0 < N_NODES)
                *(__half2*)&g_support1h[(long)r0 * HIDDEN + c] =
                    __floats2half2_rn(acc[mi][ni][0], acc[mi][ni][1]);
            if (r1 < N_NODES)
                *(__half2*)&g_support1h[(long)r1 * HIDDEN + c] =
                    __floats2half2_rn(acc[mi][ni][2], acc[mi][ni][3]);
        }
    }
}

// ---------------- SpMM1: h1h = relu(gather_sum(support1h[src]*val) + b1) ----
__global__ __launch_bounds__(256) void spmm1_kernel(const float* __restrict__ b1) {
    int warp = (blockIdx.x * blockDim.x + threadIdx.x) >> 5;
    int lane = threadIdx.x & 31;
    if (warp >= N_NODES) return;
    int beg = g_row_ptr[warp];
    int end = g_row_ptr[warp + 1];
    float4 acc = make_float4(0.f, 0.f, 0.f, 0.f);
    for (int e = beg; e < end; e++) {
        int2  ed = __ldcs(&g_edges[e]);
        float v  = __int_as_float(ed.y);
        uint2 u = *(const uint2*)&g_support1h[(long)ed.x * HIDDEN + lane * 4];
        float2 f0 = __half22float2(*(__half2*)&u.x);
        float2 f1 = __half22float2(*(__half2*)&u.y);
        acc.x += v * f0.x; acc.y += v * f0.y;
        acc.z += v * f1.x; acc.w += v * f1.y;
    }
    float4 bb = *(const float4*)&b1[lane * 4];
    acc.x = fmaxf(acc.x + bb.x, 0.f);
    acc.y = fmaxf(acc.y + bb.y, 0.f);
    acc.z = fmaxf(acc.z + bb.z, 0.f);
    acc.w = fmaxf(acc.w + bb.w, 0.f);
    uint2 o;
    *(__half2*)&o.x = __floats2half2_rn(acc.x, acc.y);
    *(__half2*)&o.y = __floats2half2_rn(acc.z, acc.w);
    *(uint2*)&g_h1h[(long)warp * HIDDEN + lane * 4] = o;
}

// ---------------- GEMM2 (fp16 tensor cores): support2h = h1h @ W2 -----------
#define H_STRIDE 136
#define G2H_SMEM ((128 * H_STRIDE + 40 * H_STRIDE) * 2)

__global__ __launch_bounds__(256) void gemm2_h_kernel(const float* __restrict__ W2) {
    extern __shared__ __half sh2[];
    __half* shH = sh2;
    __half* shW = sh2 + 128 * H_STRIDE;
    const int tid  = threadIdx.x;
    const int warp = tid >> 5;
    const int lane = tid & 31;
    const int g = lane >> 2;
    const int t = lane & 3;
    const int row0 = blockIdx.x * 128;

#pragma unroll
    for (int j = 0; j < 8; j++) {
        int chunk = tid + j * 256;
        int r = chunk >> 4;
        int c8 = (chunk & 15) * 8;
        uint4 v = make_uint4(0, 0, 0, 0);
        if (row0 + r < N_NODES)
            v = *(const uint4*)&g_h1h[(long)(row0 + r) * HIDDEN + c8];
        *(uint4*)&shH[r * H_STRIDE + c8] = v;
    }
    for (int e = tid; e < HIDDEN * NCLASS; e += 256) {
        int k = e / NCLASS, n = e % NCLASS;
        shW[n * H_STRIDE + k] = __float2half_rn(W2[e]);
    }
    __syncthreads();

    const int wm = warp * 16;
    float acc[5][4];
#pragma unroll
    for (int n = 0; n < 5; n++)
#pragma unroll
        for (int q = 0; q < 4; q++) acc[n][q] = 0.f;

#pragma unroll
    for (int ks = 0; ks < 8; ks++) {
        const int k0 = ks * 16;
        uint32_t a0 = *(uint32_t*)&shH[(wm + g)     * H_STRIDE + k0 + 2 * t];
        uint32_t a1 = *(uint32_t*)&shH[(wm + g + 8) * H_STRIDE + k0 + 2 * t];
        uint32_t a2 = *(uint32_t*)&shH[(wm + g)     * H_STRIDE + k0 + 8 + 2 * t];
        uint32_t a3 = *(uint32_t*)&shH[(wm + g + 8) * H_STRIDE + k0 + 8 + 2 * t];
#pragma unroll
        for (int n = 0; n < 5; n++) {
            uint32_t b0 = *(uint32_t*)&shW[(n * 8 + g) * H_STRIDE + k0 + 2 * t];
            uint32_t b1 = *(uint32_t*)&shW[(n * 8 + g) * H_STRIDE + k0 + 8 + 2 * t];
            asm volatile(
                "mma.sync.aligned.m16n8k16.row.col.f32.f16.f16.f32 "
                "{%0,%1,%2,%3}, {%4,%5,%6,%7}, {%8,%9}, {%0,%1,%2,%3};"
                : "+f"(acc[n][0]), "+f"(acc[n][1]), "+f"(acc[n][2]), "+f"(acc[n][3])
                : "r"(a0), "r"(a1), "r"(a2), "r"(a3), "r"(b0), "r"(b1));
        }
    }

#pragma unroll
    for (int n = 0; n < 5; n++) {
        int c = n * 8 + 2 * t;
        int r0 = row0 + wm + g;
        int r1 = r0 + 8;
        if (r0 < N_NODES)
            *(__half2*)&g_support2h[(long)r0 * NCLASS + c] =
                __floats2half2_rn(acc[n][0], acc[n][1]);
        if (r1 < N_NODES)
            *(__half2*)&g_support2h[(long)r1 * NCLASS + c] =
                __floats2half2_rn(acc[n][2], acc[n][3]);
    }
}

// ---------------- SpMM2 + bias + log_softmax --------------------------------
__global__ __launch_bounds__(256) void spmm2_softmax_kernel(const float* __restrict__ b2,
                                                            float* __restrict__ out) {
    int warp = (blockIdx.x * blockDim.x + threadIdx.x) >> 5;
    int lane = threadIdx.x & 31;
    if (warp >= N_NODES) return;
    int beg = g_row_ptr[warp];
    int end = g_row_ptr[warp + 1];
    bool act = lane < 20;
    float a0 = 0.f, a1 = 0.f;
    for (int e = beg; e < end; e++) {
        int2  ed = __ldcs(&g_edges[e]);
        float v  = __int_as_float(ed.y);
        if (act) {
            uint32_t u = *(const uint32_t*)&g_support2h[(long)ed.x * NCLASS + 2 * lane];
            float2 f = __half22float2(*(__half2*)&u);
            a0 += v * f.x;
            a1 += v * f.y;
        }
    }
    float z0 = -INFINITY, z1 = -INFINITY;
    if (act) {
        z0 = a0 + b2[2 * lane];
        z1 = a1 + b2[2 * lane + 1];
    }
    float m = fmaxf(z0, z1);
#pragma unroll
    for (int off = 16; off > 0; off >>= 1)
        m = fmaxf(m, __shfl_xor_sync(0xFFFFFFFFu, m, off));
    float s = act ? (__expf(z0 - m) + __expf(z1 - m)) : 0.f;
#pragma unroll
    for (int off = 16; off > 0; off >>= 1)
        s += __shfl_xor_sync(0xFFFFFFFFu, s, off);
    float L = m + __logf(s);
    if (act)
        *(float2*)&out[(long)warp * NCLASS + 2 * lane] = make_float2(z0 - L, z1 - L);
}

// ---------------- launch -----------------------------------------------------
extern "C" void kernel_launch(void* const* d_in, const int* in_sizes, int n_in,
                              void* d_out, int out_size) {
    const float* x        = (const float*)d_in[0];
    const int*   edge_src = (const int*)d_in[1];
    const int*   edge_dst = (const int*)d_in[2];
    const float* edge_val = (const float*)d_in[3];
    const float* W1       = (const float*)d_in[4];
    const float* b1       = (const float*)d_in[5];
    const float* W2       = (const float*)d_in[6];
    const float* b2       = (const float*)d_in[7];
    float* out = (float*)d_out;

    (void)in_sizes; (void)n_in; (void)out_size;

    static cudaStream_t s_csr = nullptr;
    static cudaEvent_t  ev_fork = nullptr, ev_join = nullptr;
    static void* p_deg = nullptr;
    static bool s_init = false;
    if (!s_init) {
        cudaStreamCreateWithFlags(&s_csr, cudaStreamNonBlocking);
        cudaEventCreateWithFlags(&ev_fork, cudaEventDisableTiming);
        cudaEventCreateWithFlags(&ev_join, cudaEventDisableTiming);
        cudaGetSymbolAddress(&p_deg, g_deg);
        cudaFuncSetAttribute(gemm2_h_kernel, cudaFuncAttributeMaxDynamicSharedMemorySize, G2H_SMEM);
        s_init = true;
    }

    cudaEventRecord(ev_fork, 0);
    cudaStreamWaitEvent(s_csr, ev_fork, 0);

    cudaMemsetAsync(p_deg, 0, N_NODES * sizeof(int), s_csr);
    hist_kernel<<<(N_EDGES + 255) / 256, 256, 0, s_csr>>>(edge_dst);
    scan_phase1<<<N_SBLOCKS, 256, 0, s_csr>>>();
    scan_phase2<<<1, 128, 0, s_csr>>>();
    scan_phase3<<<N_SBLOCKS, 256, 0, s_csr>>>();
    scatter_kernel<<<(N_EDGES + 255) / 256, 256, 0, s_csr>>>(edge_src, edge_dst, edge_val);
    cudaEventRecord(ev_join, s_csr);

    w1t_kernel<<<(NFEAT * HIDDEN + 255) / 256, 256>>>(W1);
    gemm1_f16_kernel<<<(N_NODES + G1_BM - 1) / G1_BM, 256>>>(x);

    cudaStreamWaitEvent(0, ev_join, 0);

    spmm1_kernel<<<(N_NODES * 32 + 255) / 256, 256>>>(b1);
    gemm2_h_kernel<<<(N_NODES + 127) / 128, 256, G2H_SMEM>>>(W2);
    spmm2_softmax_kernel<<<(N_NODES * 32 + 255) / 256, 256>>>(b2, out);
}